// round 4
// baseline (speedup 1.0000x reference)
#include <cuda_runtime.h>
#include <math.h>

#define NB   2
#define NPTS 8192
#define KNN  20
#define TILE 1024
#define QPB  128
#define CBUF 20

// ---------------- device scratch (no allocation allowed) ----------------
__device__ int   g_knn[NB * NPTS * KNN];
__device__ float g_S1[128], g_S2[128], g_SN[64];
__device__ float g_base1[NB][128];
__device__ float g_baseN[NB][64];

// exact-ish gelu (tanh via exp) for the tiny setup MLP
__device__ __forceinline__ float gelu_f(float x) {
    float y = 0.7978845608028654f * (x + 0.044715f * x * x * x);
    float e = __expf(2.0f * y);
    float th = 1.0f - 2.0f / (e + 1.0f);
    return 0.5f * x * (1.0f + th);
}

// fast gelu: tanh.approx.f32
__device__ __forceinline__ float gelu_fast(float x) {
    float y = 0.7978845608028654f * fmaf(0.044715f * x * x, x, x);
    float t;
    asm("tanh.approx.f32 %0, %1;" : "=f"(t) : "f"(y));
    return 0.5f * x * (1.0f + t);
}

// ---------------- kernel 1: cond MLP + folded per-batch vectors ----------------
__global__ __launch_bounds__(256) void setup_kernel(
    const float* __restrict__ t, const float* __restrict__ conditioning,
    const float* __restrict__ Wc1, const float* __restrict__ bc1,
    const float* __restrict__ Wc2, const float* __restrict__ bc2,
    const float* __restrict__ Wc3, const float* __restrict__ bc3,
    const float* __restrict__ We1, const float* __restrict__ be1,
    const float* __restrict__ Wn1, const float* __restrict__ bn1)
{
    const unsigned FULL = 0xffffffffu;
    const int tid  = threadIdx.x;
    const int lane = tid & 31;
    const int warp = tid >> 5;

    if (tid < 128) {
        float s1 = 0.f, s2 = 0.f;
#pragma unroll
        for (int c = 0; c < 36; c++) {
            s1 += We1[c * 128 + tid];
            s2 += We1[(36 + c) * 128 + tid];
        }
        g_S1[tid] = s1;
        g_S2[tid] = s2;
    }
    if (tid < 64) {
        float sn = 0.f;
#pragma unroll
        for (int c = 0; c < 36; c++) sn += Wn1[c * 64 + tid];
        g_SN[tid] = sn;
    }

    __shared__ float sc[36], h1[144], h2[144], cv[40];

    for (int b = 0; b < NB; b++) {
        if (tid < 36) {
            float v;
            if (tid < 16) {
                float f = expf(-logf(10000.0f) * (float)tid / 15.0f);
                v = sinf(t[b] * f);
            } else if (tid < 32) {
                int i = tid - 16;
                float f = expf(-logf(10000.0f) * (float)i / 15.0f);
                v = cosf(t[b] * f);
            } else {
                v = conditioning[b * 4 + (tid - 32)];
            }
            sc[tid] = v;
        }
        __syncthreads();
        if (tid < 144) {
            float a = bc1[tid];
#pragma unroll
            for (int c = 0; c < 36; c++) a = fmaf(sc[c], Wc1[c * 144 + tid], a);
            h1[tid] = gelu_f(a);
        }
        __syncthreads();
        for (int o = 0; o < 18; o++) {
            int j = warp + 8 * o;
            float a = 0.f;
#pragma unroll
            for (int r = 0; r < 5; r++) {
                int c = lane + 32 * r;
                if (c < 144) a = fmaf(h1[c], Wc2[c * 144 + j], a);
            }
#pragma unroll
            for (int off = 16; off > 0; off >>= 1)
                a += __shfl_xor_sync(FULL, a, off);
            if (lane == 0) h2[j] = gelu_f(a + bc2[j]);
        }
        __syncthreads();
        for (int o = 0; o < 5; o++) {
            int j = warp + 8 * o;
            if (j < 36) {
                float a = 0.f;
#pragma unroll
                for (int r = 0; r < 5; r++) {
                    int c = lane + 32 * r;
                    if (c < 144) a = fmaf(h2[c], Wc3[c * 36 + j], a);
                }
#pragma unroll
                for (int off = 16; off > 0; off >>= 1)
                    a += __shfl_xor_sync(FULL, a, off);
                if (lane == 0) cv[j] = a + bc3[j];
            }
        }
        __syncthreads();
        if (tid < 128) {
            float a = be1[tid];
#pragma unroll
            for (int c = 0; c < 36; c++)
                a = fmaf(cv[c], We1[c * 128 + tid] + We1[(36 + c) * 128 + tid], a);
            g_base1[b][tid] = a;
        }
        if (tid < 64) {
            float a = bn1[tid];
#pragma unroll
            for (int c = 0; c < 36; c++) a = fmaf(cv[c], Wn1[c * 64 + tid], a);
            g_baseN[b][tid] = a;
        }
        __syncthreads();
    }
}

// ---------------- kernel 2: brute-force kNN, one query per thread ----------------
// 128 threads = 128 queries; each thread scans all 8192 points (staged in smem
// tiles, warp-broadcast reads). Candidates go to a SMEM buffer (no local mem!);
// warp-ballot-triggered compaction batches the 32 lanes' insertions into
// lockstep so the 20-deep predicated insert runs for all lanes in parallel.
// No point-split -> single top-20 per query, no merge phase.
// score = 0.5*|p|^2 - q.p  (monotone in d2 for fixed query).
__global__ __launch_bounds__(128) void knn_kernel(const float* __restrict__ z)
{
    __shared__ __align__(16) float4 tile4[TILE];       // 16 KB
    __shared__ float2 cbuf[CBUF][QPB];                 // 20 KB

    const unsigned FULL = 0xffffffffu;
    const int tid = threadIdx.x;
    const int b   = blockIdx.y;
    const int q   = blockIdx.x * QPB + tid;

    const float* zb = z + (size_t)b * NPTS * 7;
    const float* zq = zb + (size_t)q * 7;
    const float qx = zq[0], qy = zq[1], qz = zq[2];

    float bd[KNN];
    int   bi[KNN];
#pragma unroll
    for (int k = 0; k < KNN; k++) { bd[k] = 1e30f; bi[k] = -1; }

    int   cnt = 0;
    float tau = 1e30f;

#define COMPACT() do {                                                        \
    for (int i = 0; i < cnt; i++) {                                           \
        float2 c = cbuf[i][tid];                                              \
        float d = c.x;                                                        \
        int  id = __float_as_int(c.y);                                        \
        if (d < bd[KNN - 1] && id != q) {                                     \
            _Pragma("unroll")                                                 \
            for (int k = KNN - 1; k > 0; --k) {                               \
                if (bd[k] > d) {                                              \
                    bool sh = bd[k - 1] > d;                                  \
                    bd[k] = sh ? bd[k - 1] : d;                               \
                    bi[k] = sh ? bi[k - 1] : id;                              \
                }                                                             \
            }                                                                 \
            if (bd[0] > d) { bd[0] = d; bi[0] = id; }                         \
        }                                                                     \
    }                                                                         \
    cnt = 0; tau = bd[KNN - 1];                                               \
} while (0)

    for (int tb = 0; tb < NPTS; tb += TILE) {
        __syncthreads();
        for (int i = tid; i < TILE; i += QPB) {
            const float* p = zb + (size_t)(tb + i) * 7;
            float x = p[0], y = p[1], w = p[2];
            tile4[i] = make_float4(x, y, w, 0.5f * (x * x + y * y + w * w));
        }
        __syncthreads();
        for (int j0 = 0; j0 < TILE; j0 += 8) {
#pragma unroll
            for (int u = 0; u < 8; u++) {
                float4 t4 = tile4[j0 + u];
                float sc = fmaf(-qz, t4.z, t4.w);
                sc = fmaf(-qy, t4.y, sc);
                sc = fmaf(-qx, t4.x, sc);
                if (sc < tau) {
                    cbuf[cnt][tid] = make_float2(sc, __int_as_float(tb + j0 + u));
                    cnt++;
                }
            }
            if (__any_sync(FULL, cnt >= CBUF - 8)) COMPACT();
        }
    }
    COMPACT();
#undef COMPACT

    int* o = g_knn + ((size_t)b * NPTS + q) * KNN;
#pragma unroll
    for (int k = 0; k < KNN; k++) o[k] = bi[k];
}

// ---------------- kernel 3: edge MLP + softmax + aggregation + node MLP ----------------
__global__ __launch_bounds__(256) void main_kernel(
    const float* __restrict__ z,
    const float* __restrict__ We1, const float* __restrict__ We2,
    const float* __restrict__ be2,
    const float* __restrict__ Wn1, const float* __restrict__ Wn2,
    const float* __restrict__ bn2,
    const float* __restrict__ alpha, const float* __restrict__ beta,
    float* __restrict__ out)
{
    const unsigned FULL = 0xffffffffu;
    const int warp = (blockIdx.x * blockDim.x + threadIdx.x) >> 5;
    const int lane = threadIdx.x & 31;
    const int b = warp >> 13;
    const int n = warp & (NPTS - 1);

    const float* zb = z + (size_t)b * NPTS * 7;
    const float* zt = zb + (size_t)n * 7;
    const float ptx = zt[0], pty = zt[1], ptz = zt[2];
    const float vtx = zt[3], vty = zt[4], vtz = zt[5];
    const float mt  = zt[6];

    float relx = 0.f, rely = 0.f, relz = 0.f;
    float vsx = 0.f, vsy = 0.f, vsz = 0.f;
    float msrc = 0.f, r2 = 0.f, dvv = 0.f, dvr = 0.f, dtr = 0.f;
    if (lane < KNN) {
        int src = g_knn[(size_t)warp * KNN + lane];
        const float* zs = zb + (size_t)src * 7;
        float sx = zs[0], sy = zs[1], sz = zs[2];
        vsx = zs[3]; vsy = zs[4]; vsz = zs[5]; msrc = zs[6];
        relx = sx - ptx; rely = sy - pty; relz = sz - ptz;
        r2  = relx * relx + rely * rely + relz * relz;
        dvv = vsx * vtx + vsy * vty + vsz * vtz;
        dvr = vsx * relx + vsy * rely + vsz * relz;
        dtr = vtx * relx + vty * rely + vtz * relz;
    }

    float s1[4], s2[4], w72[4], w73[4], w74[4], w75[4], b1[4];
    float4 we2[4];
#pragma unroll
    for (int qq = 0; qq < 4; qq++) {
        int j = lane + 32 * qq;
        s1[qq]  = g_S1[j];
        s2[qq]  = g_S2[j];
        w72[qq] = We1[72 * 128 + j];
        w73[qq] = We1[73 * 128 + j];
        w74[qq] = We1[74 * 128 + j];
        w75[qq] = We1[75 * 128 + j];
        b1[qq]  = g_base1[b][j];
        we2[qq] = ((const float4*)We2)[j];
    }

    float elog = -1e30f, esmsg = 0.f, ecrel = 0.f, ecvel = 0.f;
#pragma unroll
    for (int e = 0; e < KNN; e++) {
        float em   = __shfl_sync(FULL, msrc, e);
        float er2  = __shfl_sync(FULL, r2,   e);
        float edvv = __shfl_sync(FULL, dvv,  e);
        float edvr = __shfl_sync(FULL, dvr,  e);
        float edtr = __shfl_sync(FULL, dtr,  e);
        float p0 = 0.f, p1 = 0.f, p2 = 0.f, p3 = 0.f;
#pragma unroll
        for (int qq = 0; qq < 4; qq++) {
            float h = b1[qq];
            h = fmaf(em,   s1[qq],  h);
            h = fmaf(mt,   s2[qq],  h);
            h = fmaf(er2,  w72[qq], h);
            h = fmaf(edvv, w73[qq], h);
            h = fmaf(edvr, w74[qq], h);
            h = fmaf(edtr, w75[qq], h);
            float g = gelu_fast(h);
            p0 = fmaf(g, we2[qq].x, p0);
            p1 = fmaf(g, we2[qq].y, p1);
            p2 = fmaf(g, we2[qq].z, p2);
            p3 = fmaf(g, we2[qq].w, p3);
        }
#pragma unroll
        for (int off = 16; off > 0; off >>= 1) {
            p0 += __shfl_xor_sync(FULL, p0, off);
            p1 += __shfl_xor_sync(FULL, p1, off);
            p2 += __shfl_xor_sync(FULL, p2, off);
            p3 += __shfl_xor_sync(FULL, p3, off);
        }
        if (lane == e) {
            elog  = p0 + be2[0];
            esmsg = p1 + be2[1];
            ecrel = p2 + be2[2];
            ecvel = p3 + be2[3];
        }
    }

    float lg = (lane < KNN) ? elog : -1e30f;
    float mx = lg;
#pragma unroll
    for (int off = 16; off > 0; off >>= 1)
        mx = fmaxf(mx, __shfl_xor_sync(FULL, mx, off));
    float a = (lane < KNN) ? __expf(lg - mx) : 0.f;
    float den = a;
#pragma unroll
    for (int off = 16; off > 0; off >>= 1)
        den += __shfl_xor_sync(FULL, den, off);
    float w = a / den;

    float vmx = w * (ecrel * relx + ecvel * vsx);
    float vmy = w * (ecrel * rely + ecvel * vsy);
    float vmz = w * (ecrel * relz + ecvel * vsz);
    float sg  = w * esmsg;
#pragma unroll
    for (int off = 16; off > 0; off >>= 1) {
        vmx += __shfl_xor_sync(FULL, vmx, off);
        vmy += __shfl_xor_sync(FULL, vmy, off);
        vmz += __shfl_xor_sync(FULL, vmz, off);
        sg  += __shfl_xor_sync(FULL, sg,  off);
    }

    float acc = 0.f;
#pragma unroll
    for (int qq = 0; qq < 2; qq++) {
        int j = lane + 32 * qq;
        float h = g_baseN[b][j];
        h = fmaf(mt, g_SN[j], h);
        h = fmaf(sg, Wn1[36 * 64 + j], h);
        acc = fmaf(gelu_fast(h), Wn2[j], acc);
    }
#pragma unroll
    for (int off = 16; off > 0; off >>= 1)
        acc += __shfl_xor_sync(FULL, acc, off);

    if (lane == 0) {
        float sout = acc + bn2[0];
        float al = alpha[0], be = beta[0];
        float* o = out + (size_t)warp * 7;
        o[0] = ptx + (ptx + al * vmx);
        o[1] = pty + (pty + al * vmy);
        o[2] = ptz + (ptz + al * vmz);
        o[3] = vtx + be * vmx;
        o[4] = vty + be * vmy;
        o[5] = vtz + be * vmz;
        o[6] = mt + sout;
    }
}

// ---------------- launch ----------------
extern "C" void kernel_launch(void* const* d_in, const int* in_sizes, int n_in,
                              void* d_out, int out_size)
{
    const float* z    = (const float*)d_in[0];
    const float* t    = (const float*)d_in[1];
    const float* cond = (const float*)d_in[2];
    const float* Wc1 = (const float*)d_in[4];
    const float* bc1 = (const float*)d_in[5];
    const float* Wc2 = (const float*)d_in[6];
    const float* bc2 = (const float*)d_in[7];
    const float* Wc3 = (const float*)d_in[8];
    const float* bc3 = (const float*)d_in[9];
    const float* We1 = (const float*)d_in[10];
    const float* be1 = (const float*)d_in[11];
    const float* We2 = (const float*)d_in[12];
    const float* be2 = (const float*)d_in[13];
    const float* Wn1 = (const float*)d_in[14];
    const float* bn1 = (const float*)d_in[15];
    const float* Wn2 = (const float*)d_in[16];
    const float* bn2 = (const float*)d_in[17];
    const float* alpha = (const float*)d_in[18];
    const float* beta  = (const float*)d_in[19];
    float* out = (float*)d_out;

    dim3 kg(NPTS / QPB, NB);
    knn_kernel<<<kg, QPB>>>(z);

    setup_kernel<<<1, 256>>>(t, cond, Wc1, bc1, Wc2, bc2, Wc3, bc3,
                             We1, be1, Wn1, bn1);

    int total_warps = NB * NPTS;
    int blocks = total_warps / 8;
    main_kernel<<<blocks, 256>>>(z, We1, We2, be2, Wn1, Wn2, bn2,
                                 alpha, beta, out);
}

// round 5
// speedup vs baseline: 2.2555x; 2.2555x over previous
#include <cuda_runtime.h>
#include <math.h>

#define NB   2
#define NPTS 8192
#define KNN  20
#define TILE 1024
#define QPB  32          // queries per knn block
#define NSPL 4           // point splits (warps per knn block)
#define KTHR (QPB*NSPL)  // 128 threads
#define CBUF 16

// ---------------- device scratch (no allocation allowed) ----------------
__device__ int   g_knn[NB * NPTS * KNN];
__device__ float g_S1[128], g_S2[128], g_SN[64];
__device__ float g_base1[NB][128];
__device__ float g_baseN[NB][64];

// exact-ish gelu (tanh via exp) for the tiny setup MLP
__device__ __forceinline__ float gelu_f(float x) {
    float y = 0.7978845608028654f * (x + 0.044715f * x * x * x);
    float e = __expf(2.0f * y);
    float th = 1.0f - 2.0f / (e + 1.0f);
    return 0.5f * x * (1.0f + th);
}

// fast gelu: tanh.approx.f32
__device__ __forceinline__ float gelu_fast(float x) {
    float y = 0.7978845608028654f * fmaf(0.044715f * x * x, x, x);
    float t;
    asm("tanh.approx.f32 %0, %1;" : "=f"(t) : "f"(y));
    return 0.5f * x * (1.0f + t);
}

// ---------------- kernel 1: cond MLP + folded per-batch vectors ----------------
__global__ __launch_bounds__(256) void setup_kernel(
    const float* __restrict__ t, const float* __restrict__ conditioning,
    const float* __restrict__ Wc1, const float* __restrict__ bc1,
    const float* __restrict__ Wc2, const float* __restrict__ bc2,
    const float* __restrict__ Wc3, const float* __restrict__ bc3,
    const float* __restrict__ We1, const float* __restrict__ be1,
    const float* __restrict__ Wn1, const float* __restrict__ bn1)
{
    const unsigned FULL = 0xffffffffu;
    const int tid  = threadIdx.x;
    const int lane = tid & 31;
    const int warp = tid >> 5;

    if (tid < 128) {
        float s1 = 0.f, s2 = 0.f;
#pragma unroll
        for (int c = 0; c < 36; c++) {
            s1 += We1[c * 128 + tid];
            s2 += We1[(36 + c) * 128 + tid];
        }
        g_S1[tid] = s1;
        g_S2[tid] = s2;
    }
    if (tid < 64) {
        float sn = 0.f;
#pragma unroll
        for (int c = 0; c < 36; c++) sn += Wn1[c * 64 + tid];
        g_SN[tid] = sn;
    }

    __shared__ float sc[36], h1[144], h2[144], cv[40];

    for (int b = 0; b < NB; b++) {
        if (tid < 36) {
            float v;
            if (tid < 16) {
                float f = expf(-logf(10000.0f) * (float)tid / 15.0f);
                v = sinf(t[b] * f);
            } else if (tid < 32) {
                int i = tid - 16;
                float f = expf(-logf(10000.0f) * (float)i / 15.0f);
                v = cosf(t[b] * f);
            } else {
                v = conditioning[b * 4 + (tid - 32)];
            }
            sc[tid] = v;
        }
        __syncthreads();
        if (tid < 144) {
            float a = bc1[tid];
#pragma unroll
            for (int c = 0; c < 36; c++) a = fmaf(sc[c], Wc1[c * 144 + tid], a);
            h1[tid] = gelu_f(a);
        }
        __syncthreads();
        for (int o = 0; o < 18; o++) {
            int j = warp + 8 * o;
            float a = 0.f;
#pragma unroll
            for (int r = 0; r < 5; r++) {
                int c = lane + 32 * r;
                if (c < 144) a = fmaf(h1[c], Wc2[c * 144 + j], a);
            }
#pragma unroll
            for (int off = 16; off > 0; off >>= 1)
                a += __shfl_xor_sync(FULL, a, off);
            if (lane == 0) h2[j] = gelu_f(a + bc2[j]);
        }
        __syncthreads();
        for (int o = 0; o < 5; o++) {
            int j = warp + 8 * o;
            if (j < 36) {
                float a = 0.f;
#pragma unroll
                for (int r = 0; r < 5; r++) {
                    int c = lane + 32 * r;
                    if (c < 144) a = fmaf(h2[c], Wc3[c * 36 + j], a);
                }
#pragma unroll
                for (int off = 16; off > 0; off >>= 1)
                    a += __shfl_xor_sync(FULL, a, off);
                if (lane == 0) cv[j] = a + bc3[j];
            }
        }
        __syncthreads();
        if (tid < 128) {
            float a = be1[tid];
#pragma unroll
            for (int c = 0; c < 36; c++)
                a = fmaf(cv[c], We1[c * 128 + tid] + We1[(36 + c) * 128 + tid], a);
            g_base1[b][tid] = a;
        }
        if (tid < 64) {
            float a = bn1[tid];
#pragma unroll
            for (int c = 0; c < 36; c++) a = fmaf(cv[c], Wn1[c * 64 + tid], a);
            g_baseN[b][tid] = a;
        }
        __syncthreads();
    }
}

// ---------------- kernel 2: brute-force kNN ----------------
// 128 threads = 32 queries x 4 point-splits. Warp = split, lanes = queries
// (tile reads are warp-broadcast). SMEM candidate buffer + ballot-batched
// compaction. The 4 splits of a query share a tau upper bound through smem
// (benign non-atomic fmin race: any stored value is some split's 20th-best,
// hence a valid upper bound on the global 20th), so total insertions per
// query stay near the single-scan minimum.
// score = 0.5*|p|^2 - q.p  (monotone in d2 for fixed query).
__global__ __launch_bounds__(KTHR) void knn_kernel(const float* __restrict__ z)
{
    __shared__ __align__(16) unsigned char raw[32768];
    __shared__ float tau_sh[QPB];
    float4* tile4 = (float4*)raw;                            // 16 KB
    float2 (*cbuf)[KTHR] = (float2 (*)[KTHR])(raw + 16384);  // 16 KB

    const unsigned FULL = 0xffffffffu;
    const int tid = threadIdx.x;
    const int b   = blockIdx.y;
    const int lq  = tid & 31;                 // query lane
    const int s   = tid >> 5;                 // split = warp
    const int q   = blockIdx.x * QPB + lq;

    const float* zb = z + (size_t)b * NPTS * 7;
    const float* zq = zb + (size_t)q * 7;
    const float qx = zq[0], qy = zq[1], qz = zq[2];

    if (tid < QPB) tau_sh[tid] = 1e30f;

    float bd[KNN];
    int   bi[KNN];
#pragma unroll
    for (int k = 0; k < KNN; k++) { bd[k] = 1e30f; bi[k] = -1; }

    int   cnt = 0;
    float tau = 1e30f;

#define COMPACT() do {                                                        \
    for (int i = 0; i < cnt; i++) {                                           \
        float2 c = cbuf[i][tid];                                              \
        float d = c.x;                                                        \
        int  id = __float_as_int(c.y);                                        \
        if (d < bd[KNN - 1] && id != q) {                                     \
            _Pragma("unroll")                                                 \
            for (int k = KNN - 1; k > 0; --k) {                               \
                if (bd[k] > d) {                                              \
                    bool sh = bd[k - 1] > d;                                  \
                    bd[k] = sh ? bd[k - 1] : d;                               \
                    bi[k] = sh ? bi[k - 1] : id;                              \
                }                                                             \
            }                                                                 \
            if (bd[0] > d) { bd[0] = d; bi[0] = id; }                         \
        }                                                                     \
    }                                                                         \
    cnt = 0;                                                                  \
    tau_sh[lq] = fminf(tau_sh[lq], bd[KNN - 1]);                              \
    tau = fminf(bd[KNN - 1], tau_sh[lq]);                                     \
} while (0)

    for (int tb = 0; tb < NPTS; tb += TILE) {
        __syncthreads();
        for (int i = tid; i < TILE; i += KTHR) {
            const float* p = zb + (size_t)(tb + i) * 7;
            float x = p[0], y = p[1], w = p[2];
            tile4[i] = make_float4(x, y, w, 0.5f * (x * x + y * y + w * w));
        }
        __syncthreads();
        const int jb = s * (TILE / NSPL);
        for (int j0 = jb; j0 < jb + TILE / NSPL; j0 += 8) {
#pragma unroll
            for (int u = 0; u < 8; u++) {
                float4 t4 = tile4[j0 + u];
                float scv = fmaf(-qz, t4.z, t4.w);
                scv = fmaf(-qy, t4.y, scv);
                scv = fmaf(-qx, t4.x, scv);
                if (scv < tau) {
                    cbuf[cnt][tid] = make_float2(scv, __int_as_float(tb + j0 + u));
                    cnt++;
                }
            }
            if (__any_sync(FULL, cnt >= CBUF - 8)) COMPACT();
        }
    }
    COMPACT();
#undef COMPACT

    __syncthreads();   // done with tile/cbuf; reuse raw for the 4-way merge
    float* md = (float*)raw;                         // 80*32*4 = 10240 B
    int*   mi = (int*)(raw + NSPL * KNN * QPB * 4);  // 10240 B
#pragma unroll
    for (int k = 0; k < KNN; k++) {
        md[(s * KNN + k) * QPB + lq] = bd[k];
        mi[(s * KNN + k) * QPB + lq] = bi[k];
    }
    __syncthreads();

    if (tid < QPB) {
        float fd[KNN]; int fi[KNN];
#pragma unroll
        for (int k = 0; k < KNN; k++) { fd[k] = 1e30f; fi[k] = -1; }
        for (int i = 0; i < NSPL * KNN; i++) {
            float d = md[i * QPB + tid];
            int  id = mi[i * QPB + tid];
            if (d < fd[KNN - 1]) {
#pragma unroll
                for (int k = KNN - 1; k > 0; --k) {
                    if (fd[k] > d) {
                        bool sh = fd[k - 1] > d;
                        fd[k] = sh ? fd[k - 1] : d;
                        fi[k] = sh ? fi[k - 1] : id;
                    }
                }
                if (fd[0] > d) { fd[0] = d; fi[0] = id; }
            }
        }
        int qq = blockIdx.x * QPB + tid;
        int* o = g_knn + ((size_t)b * NPTS + qq) * KNN;
#pragma unroll
        for (int k = 0; k < KNN; k++) o[k] = fi[k];
    }
}

// ---------------- kernel 3: edge MLP + softmax + aggregation + node MLP ----------------
// one warp per node. Per edge: lanes compute 4-unit partials, fold xor16,
// store one float4 (lanes 0-15). After the edge loop a single transpose-
// reduce gives lane e its edge's 4 outputs (replaces 20x 5-step butterflies).
__global__ __launch_bounds__(256) void main_kernel(
    const float* __restrict__ z,
    const float* __restrict__ We1, const float* __restrict__ We2,
    const float* __restrict__ be2,
    const float* __restrict__ Wn1, const float* __restrict__ Wn2,
    const float* __restrict__ bn2,
    const float* __restrict__ alpha, const float* __restrict__ beta,
    float* __restrict__ out)
{
    __shared__ float4 part[8][KNN][17];   // 8 warps * 20 edges * 16(+1 pad) = 43.5 KB

    const unsigned FULL = 0xffffffffu;
    const int wlocal = threadIdx.x >> 5;
    const int warp = (blockIdx.x * blockDim.x + threadIdx.x) >> 5;
    const int lane = threadIdx.x & 31;
    const int b = warp >> 13;
    const int n = warp & (NPTS - 1);

    const float* zb = z + (size_t)b * NPTS * 7;
    const float* zt = zb + (size_t)n * 7;
    const float ptx = zt[0], pty = zt[1], ptz = zt[2];
    const float vtx = zt[3], vty = zt[4], vtz = zt[5];
    const float mt  = zt[6];

    float relx = 0.f, rely = 0.f, relz = 0.f;
    float vsx = 0.f, vsy = 0.f, vsz = 0.f;
    float msrc = 0.f, r2 = 0.f, dvv = 0.f, dvr = 0.f, dtr = 0.f;
    if (lane < KNN) {
        int src = g_knn[(size_t)warp * KNN + lane];
        const float* zs = zb + (size_t)src * 7;
        float sx = zs[0], sy = zs[1], sz = zs[2];
        vsx = zs[3]; vsy = zs[4]; vsz = zs[5]; msrc = zs[6];
        relx = sx - ptx; rely = sy - pty; relz = sz - ptz;
        r2  = relx * relx + rely * rely + relz * relz;
        dvv = vsx * vtx + vsy * vty + vsz * vtz;
        dvr = vsx * relx + vsy * rely + vsz * relz;
        dtr = vtx * relx + vty * rely + vtz * relz;
    }

    float s1[4], s2[4], w72[4], w73[4], w74[4], w75[4], b1[4];
    float4 we2[4];
#pragma unroll
    for (int qq = 0; qq < 4; qq++) {
        int j = lane + 32 * qq;
        s1[qq]  = g_S1[j];
        s2[qq]  = g_S2[j];
        w72[qq] = We1[72 * 128 + j];
        w73[qq] = We1[73 * 128 + j];
        w74[qq] = We1[74 * 128 + j];
        w75[qq] = We1[75 * 128 + j];
        b1[qq]  = g_base1[b][j];
        we2[qq] = ((const float4*)We2)[j];
    }

#pragma unroll
    for (int e = 0; e < KNN; e++) {
        float em   = __shfl_sync(FULL, msrc, e);
        float er2  = __shfl_sync(FULL, r2,   e);
        float edvv = __shfl_sync(FULL, dvv,  e);
        float edvr = __shfl_sync(FULL, dvr,  e);
        float edtr = __shfl_sync(FULL, dtr,  e);
        float p0 = 0.f, p1 = 0.f, p2 = 0.f, p3 = 0.f;
#pragma unroll
        for (int qq = 0; qq < 4; qq++) {
            float h = b1[qq];
            h = fmaf(em,   s1[qq],  h);
            h = fmaf(mt,   s2[qq],  h);
            h = fmaf(er2,  w72[qq], h);
            h = fmaf(edvv, w73[qq], h);
            h = fmaf(edvr, w74[qq], h);
            h = fmaf(edtr, w75[qq], h);
            float g = gelu_fast(h);
            p0 = fmaf(g, we2[qq].x, p0);
            p1 = fmaf(g, we2[qq].y, p1);
            p2 = fmaf(g, we2[qq].z, p2);
            p3 = fmaf(g, we2[qq].w, p3);
        }
        // fold 32 -> 16 partials
        p0 += __shfl_xor_sync(FULL, p0, 16);
        p1 += __shfl_xor_sync(FULL, p1, 16);
        p2 += __shfl_xor_sync(FULL, p2, 16);
        p3 += __shfl_xor_sync(FULL, p3, 16);
        if (lane < 16) part[wlocal][e][lane] = make_float4(p0, p1, p2, p3);
    }
    __syncwarp();

    // transpose-reduce: lane e sums its edge's 16 partials
    float elog = -1e30f, esmsg = 0.f, ecrel = 0.f, ecvel = 0.f;
    if (lane < KNN) {
        float4 acc = part[wlocal][lane][0];
#pragma unroll
        for (int i = 1; i < 16; i++) {
            float4 p = part[wlocal][lane][i];
            acc.x += p.x; acc.y += p.y; acc.z += p.z; acc.w += p.w;
        }
        elog  = acc.x + be2[0];
        esmsg = acc.y + be2[1];
        ecrel = acc.z + be2[2];
        ecvel = acc.w + be2[3];
    }

    float lg = (lane < KNN) ? elog : -1e30f;
    float mx = lg;
#pragma unroll
    for (int off = 16; off > 0; off >>= 1)
        mx = fmaxf(mx, __shfl_xor_sync(FULL, mx, off));
    float a = (lane < KNN) ? __expf(lg - mx) : 0.f;
    float den = a;
#pragma unroll
    for (int off = 16; off > 0; off >>= 1)
        den += __shfl_xor_sync(FULL, den, off);
    float w = a / den;

    float vmx = w * (ecrel * relx + ecvel * vsx);
    float vmy = w * (ecrel * rely + ecvel * vsy);
    float vmz = w * (ecrel * relz + ecvel * vsz);
    float sg  = w * esmsg;
#pragma unroll
    for (int off = 16; off > 0; off >>= 1) {
        vmx += __shfl_xor_sync(FULL, vmx, off);
        vmy += __shfl_xor_sync(FULL, vmy, off);
        vmz += __shfl_xor_sync(FULL, vmz, off);
        sg  += __shfl_xor_sync(FULL, sg,  off);
    }

    float acc2 = 0.f;
#pragma unroll
    for (int qq = 0; qq < 2; qq++) {
        int j = lane + 32 * qq;
        float h = g_baseN[b][j];
        h = fmaf(mt, g_SN[j], h);
        h = fmaf(sg, Wn1[36 * 64 + j], h);
        acc2 = fmaf(gelu_fast(h), Wn2[j], acc2);
    }
#pragma unroll
    for (int off = 16; off > 0; off >>= 1)
        acc2 += __shfl_xor_sync(FULL, acc2, off);

    if (lane == 0) {
        float sout = acc2 + bn2[0];
        float al = alpha[0], be = beta[0];
        float* o = out + (size_t)warp * 7;
        o[0] = ptx + (ptx + al * vmx);
        o[1] = pty + (pty + al * vmy);
        o[2] = ptz + (ptz + al * vmz);
        o[3] = vtx + be * vmx;
        o[4] = vty + be * vmy;
        o[5] = vtz + be * vmz;
        o[6] = mt + sout;
    }
}

// ---------------- launch ----------------
extern "C" void kernel_launch(void* const* d_in, const int* in_sizes, int n_in,
                              void* d_out, int out_size)
{
    const float* z    = (const float*)d_in[0];
    const float* t    = (const float*)d_in[1];
    const float* cond = (const float*)d_in[2];
    const float* Wc1 = (const float*)d_in[4];
    const float* bc1 = (const float*)d_in[5];
    const float* Wc2 = (const float*)d_in[6];
    const float* bc2 = (const float*)d_in[7];
    const float* Wc3 = (const float*)d_in[8];
    const float* bc3 = (const float*)d_in[9];
    const float* We1 = (const float*)d_in[10];
    const float* be1 = (const float*)d_in[11];
    const float* We2 = (const float*)d_in[12];
    const float* be2 = (const float*)d_in[13];
    const float* Wn1 = (const float*)d_in[14];
    const float* bn1 = (const float*)d_in[15];
    const float* Wn2 = (const float*)d_in[16];
    const float* bn2 = (const float*)d_in[17];
    const float* alpha = (const float*)d_in[18];
    const float* beta  = (const float*)d_in[19];
    float* out = (float*)d_out;

    dim3 kg(NPTS / QPB, NB);
    knn_kernel<<<kg, KTHR>>>(z);

    setup_kernel<<<1, 256>>>(t, cond, Wc1, bc1, Wc2, bc2, Wc3, bc3,
                             We1, be1, Wn1, bn1);

    int total_warps = NB * NPTS;
    int blocks = total_warps / 8;
    main_kernel<<<blocks, 256>>>(z, We1, We2, be2, Wn1, Wn2, bn2,
                                 alpha, beta, out);
}